// round 3
// baseline (speedup 1.0000x reference)
#include <cuda_runtime.h>
#include <cuda_bf16.h>
#include <math.h>

// ---------------- problem constants ----------------
#define BATCH 8
#define NA    1614          // anchors
#define TOPN  6
#define OUTP  224
// conv1: rpn (8,2048,14,14) -> d1 (8,128,14,14), 3x3 pad1
// GEMM: M=128, N=8*196=1568, K=2048*9=18432
#define GN    1568
#define GK    18432
#define KSPL  8
#define KPB   (GK / KSPL)   // 2304

// output layout (flattened tuple, float32)
#define OFF_COORDS 7225344  // 48*3*224*224
#define OFF_PROB   7225536
#define OFF_IDX    7225584

// ---------------- scratch (device globals; no allocations allowed) ----------------
__device__ float g_part[KSPL][128][GN];     // conv1 K-split partials (~6.4MB)
__device__ float g_d1[BATCH][128][196];     // post-relu
__device__ float g_d2[BATCH][128][49];
__device__ float g_d3[BATCH][128][16];
__device__ float g_scores[BATCH][NA];
__device__ int   g_boxes[BATCH][TOPN][4];   // x0,y0,x1,y1 (ints, padded coords)

// ---------------- conv1 as implicit GEMM with K-split ----------------
// grid (25 n-tiles, 8 k-splits), 256 threads. C tile 128x64, thread tile 8x4.
__global__ __launch_bounds__(256) void conv1_gemm(const float* __restrict__ rpn,
                                                  const float* __restrict__ wd1) {
    __shared__ float As[16][132];   // [k][oc], padded to soften STS conflicts
    __shared__ float Bs[16][64];    // [k][px]

    const int t = threadIdx.x;
    const int n_base = blockIdx.x * 64;
    const int ks = blockIdx.y;

    // ---- B (im2col) per-thread invariants ----
    const int pn = t & 63;
    const int nn = n_base + pn;
    const bool nvalid = (nn < GN);
    const int nc = nvalid ? nn : 0;
    const int bb = nc / 196;
    const int pp = nc % 196;
    const int oy = pp / 14, ox = pp % 14;
    const int kk_b0 = t >> 6;                 // 0..3
    int ic[4], t9[4];
#pragma unroll
    for (int i = 0; i < 4; ++i) {
        int k = ks * KPB + kk_b0 + 4 * i;
        ic[i] = k / 9; t9[i] = k % 9;
    }
    const float* rbase = rpn + (size_t)bb * 2048 * 196;

    // ---- A per-thread invariants: wd1 viewed as [128][18432] ----
    const int kkA = (t & 3) * 4;
    const int ocA = t >> 2;                    // 0..63 (second row = +64)
    const float* pA0 = wd1 + (size_t)ocA * GK + ks * KPB + kkA;
    const float* pA1 = pA0 + (size_t)64 * GK;

    const int tm = t >> 4;     // 0..15 -> oc block of 8
    const int tn = t & 15;     // 0..15 -> px block of 4

    float acc[8][4];
#pragma unroll
    for (int r = 0; r < 8; ++r)
#pragma unroll
        for (int c = 0; c < 4; ++c) acc[r][c] = 0.f;

    for (int ch = 0; ch < KPB / 16; ++ch) {
        // global loads (independent of smem)
        float4 a0 = *(const float4*)pA0;
        float4 a1 = *(const float4*)pA1;
        pA0 += 16; pA1 += 16;

        float bv[4];
#pragma unroll
        for (int i = 0; i < 4; ++i) {
            int ky = t9[i] / 3, kx = t9[i] - 3 * (t9[i] / 3);
            int iy = oy + ky - 1, ix = ox + kx - 1;
            bool inb = nvalid && ((unsigned)iy < 14u) && ((unsigned)ix < 14u);
            bv[i] = inb ? rbase[ic[i] * 196 + iy * 14 + ix] : 0.f;
        }

        __syncthreads();
        As[kkA + 0][ocA] = a0.x; As[kkA + 1][ocA] = a0.y;
        As[kkA + 2][ocA] = a0.z; As[kkA + 3][ocA] = a0.w;
        As[kkA + 0][ocA + 64] = a1.x; As[kkA + 1][ocA + 64] = a1.y;
        As[kkA + 2][ocA + 64] = a1.z; As[kkA + 3][ocA + 64] = a1.w;
#pragma unroll
        for (int i = 0; i < 4; ++i) Bs[kk_b0 + 4 * i][pn] = bv[i];
        __syncthreads();

#pragma unroll
        for (int kk = 0; kk < 16; ++kk) {
            float4 af0 = *(const float4*)&As[kk][tm * 8];
            float4 af1 = *(const float4*)&As[kk][tm * 8 + 4];
            float4 bf  = *(const float4*)&Bs[kk][tn * 4];
            float av[8] = {af0.x, af0.y, af0.z, af0.w, af1.x, af1.y, af1.z, af1.w};
            float bw[4] = {bf.x, bf.y, bf.z, bf.w};
#pragma unroll
            for (int r = 0; r < 8; ++r)
#pragma unroll
                for (int c = 0; c < 4; ++c) acc[r][c] += av[r] * bw[c];
        }

        // advance k by 16: ic/t9 incremental update (16 mod 9 = 7)
#pragma unroll
        for (int i = 0; i < 4; ++i) {
            t9[i] += 7; ic[i] += 1;
            if (t9[i] >= 9) { t9[i] -= 9; ic[i] += 1; }
        }
    }

    const int n0 = n_base + tn * 4;
    if (n0 < GN) {
#pragma unroll
        for (int r = 0; r < 8; ++r) {
            int oc = tm * 8 + r;
            float4 v = make_float4(acc[r][0], acc[r][1], acc[r][2], acc[r][3]);
            *(float4*)&g_part[ks][oc][n0] = v;
        }
    }
}

// sum K-split partials + bias + relu -> g_d1
__global__ void reduce_relu_kernel(const float* __restrict__ bd1) {
    int i = blockIdx.x * 256 + threadIdx.x;
    if (i >= 128 * GN) return;
    int oc = i / GN, n = i - oc * GN;
    float s = bd1[oc];
#pragma unroll
    for (int ks = 0; ks < KSPL; ++ks) s += g_part[ks][oc][n];
    int b = n / 196, p = n - b * 196;
    g_d1[b][oc][p] = fmaxf(s, 0.f);
}

// ---------------- conv2: d1(14x14) -> d2(7x7), 3x3 stride2 pad1 ----------------
__global__ void conv2_kernel(const float* __restrict__ wd2, const float* __restrict__ bd2) {
    int b = blockIdx.x, oc = blockIdx.y;
    int t = threadIdx.x;
    if (t >= 49) return;
    int oy = t / 7, ox = t - 7 * (t / 7);
    float acc = bd2[oc];
    const float* w0 = wd2 + (size_t)oc * 128 * 9;
    for (int ic = 0; ic < 128; ++ic) {
        const float* dp = &g_d1[b][ic][0];
        const float* wp = w0 + ic * 9;
#pragma unroll
        for (int ky = 0; ky < 3; ++ky) {
            int iy = 2 * oy - 1 + ky;
            if ((unsigned)iy >= 14u) continue;
#pragma unroll
            for (int kx = 0; kx < 3; ++kx) {
                int ix = 2 * ox - 1 + kx;
                if ((unsigned)ix < 14u) acc += dp[iy * 14 + ix] * wp[ky * 3 + kx];
            }
        }
    }
    g_d2[b][oc][t] = fmaxf(acc, 0.f);
}

// ---------------- conv3: d2(7x7) -> d3(4x4), 3x3 stride2 pad1 ----------------
__global__ void conv3_kernel(const float* __restrict__ wd3, const float* __restrict__ bd3) {
    int b = blockIdx.x, oc = blockIdx.y;
    int t = threadIdx.x;
    if (t >= 16) return;
    int oy = t >> 2, ox = t & 3;
    float acc = bd3[oc];
    const float* w0 = wd3 + (size_t)oc * 128 * 9;
    for (int ic = 0; ic < 128; ++ic) {
        const float* dp = &g_d2[b][ic][0];
        const float* wp = w0 + ic * 9;
#pragma unroll
        for (int ky = 0; ky < 3; ++ky) {
            int iy = 2 * oy - 1 + ky;
            if ((unsigned)iy >= 7u) continue;
#pragma unroll
            for (int kx = 0; kx < 3; ++kx) {
                int ix = 2 * ox - 1 + kx;
                if ((unsigned)ix < 7u) acc += dp[iy * 7 + ix] * wp[ky * 3 + kx];
            }
        }
    }
    g_d3[b][oc][t] = fmaxf(acc, 0.f);
}

// ---------------- 1x1 score heads -> g_scores ----------------
__global__ void heads_kernel(const float* __restrict__ wt1, const float* __restrict__ bt1,
                             const float* __restrict__ wt2, const float* __restrict__ bt2,
                             const float* __restrict__ wt3, const float* __restrict__ bt3) {
    int b = blockIdx.x;
    int a = blockIdx.y * 256 + threadIdx.x;
    if (a >= NA) return;
    float acc;
    if (a < 1176) {
        int c = a / 196, p = a - c * 196;
        acc = bt1[c];
        const float* w = wt1 + c * 128;
        for (int ic = 0; ic < 128; ++ic) acc += g_d1[b][ic][p] * w[ic];
    } else if (a < 1470) {
        int a2 = a - 1176;
        int c = a2 / 49, p = a2 - c * 49;
        acc = bt2[c];
        const float* w = wt2 + c * 128;
        for (int ic = 0; ic < 128; ++ic) acc += g_d2[b][ic][p] * w[ic];
    } else {
        int a3 = a - 1470;
        int c = a3 / 16, p = a3 & 15;
        acc = bt3[c];
        const float* w = wt3 + c * 128;
        for (int ic = 0; ic < 128; ++ic) acc += g_d3[b][ic][p] * w[ic];
    }
    g_scores[b][a] = acc;
}

// ---------------- NMS + top-6 per batch ----------------
// Key: (sortable(score) << 32) | ~idx  -> descending sort = score desc, idx asc (stable).
// Greedy NMS only needs comparison against kept-so-far; stop at 6 kept.
__global__ void nms_topk_kernel(const float* __restrict__ anchors, float* __restrict__ out) {
    __shared__ unsigned long long key[2048];
    const int b = blockIdx.x;
    const int tid = threadIdx.x;

    for (int a = tid; a < 2048; a += 512) {
        unsigned long long k = 0ull;
        if (a < NA) {
            unsigned u = __float_as_uint(g_scores[b][a]);
            unsigned us = (u & 0x80000000u) ? ~u : (u | 0x80000000u);
            k = ((unsigned long long)us << 32) | (unsigned)(~(unsigned)a);
        }
        key[a] = k;
    }

    for (int kk = 2; kk <= 2048; kk <<= 1) {
        for (int j = kk >> 1; j > 0; j >>= 1) {
            __syncthreads();
            for (int i = tid; i < 2048; i += 512) {
                int ixj = i ^ j;
                if (ixj > i) {
                    unsigned long long x = key[i], y = key[ixj];
                    bool desc = ((i & kk) == 0);
                    if (desc ? (x < y) : (x > y)) { key[i] = y; key[ixj] = x; }
                }
            }
        }
    }
    __syncthreads();

    if (tid == 0) {
        float ky0[TOPN], kx0[TOPN], ky1[TOPN], kx1[TOPN], karea[TOPN], kprob[TOPN];
        int kidx[TOPN];
        int nk = 0;
        for (int r = 0; r < NA && nk < TOPN; ++r) {
            unsigned long long k = key[r];
            int idx = (int)(~(unsigned)k);
            if (idx >= NA) break;   // padding (shouldn't happen before r==NA)
            float y0 = anchors[idx * 4 + 0], x0 = anchors[idx * 4 + 1];
            float y1 = anchors[idx * 4 + 2], x1 = anchors[idx * 4 + 3];
            float area = (y1 - y0) * (x1 - x0);
            bool sup = false;
            for (int s = 0; s < nk; ++s) {
                float ih = fminf(y1, ky1[s]) - fmaxf(y0, ky0[s]); if (ih < 0.f) ih = 0.f;
                float iw = fminf(x1, kx1[s]) - fmaxf(x0, kx0[s]); if (iw < 0.f) iw = 0.f;
                float inter = ih * iw;
                // exact integer comparison: inter/den > 0.25  <=>  inter > 0.25*den
                if (inter > 0.25f * (area + karea[s] - inter)) { sup = true; break; }
            }
            if (!sup) {
                unsigned us = (unsigned)(k >> 32);
                unsigned u = (us & 0x80000000u) ? (us ^ 0x80000000u) : ~us;
                ky0[nk] = y0; kx0[nk] = x0; ky1[nk] = y1; kx1[nk] = x1;
                karea[nk] = area; kidx[nk] = idx; kprob[nk] = __uint_as_float(u);
                ++nk;
            }
        }
        // degenerate fill (<6 kept): lowest-index non-kept anchors with -inf (matches top_k on -inf ties)
        int fi = 0;
        while (nk < TOPN) {
            bool used = false;
            for (int s = 0; s < nk; ++s) if (kidx[s] == fi) used = true;
            if (!used) {
                ky0[nk] = anchors[fi * 4 + 0]; kx0[nk] = anchors[fi * 4 + 1];
                ky1[nk] = anchors[fi * 4 + 2]; kx1[nk] = anchors[fi * 4 + 3];
                karea[nk] = 0.f; kidx[nk] = fi; kprob[nk] = -INFINITY;
                ++nk;
            }
            ++fi;
        }
        for (int s = 0; s < TOPN; ++s) {
            int o = b * TOPN + s;
            g_boxes[b][s][0] = (int)kx0[s];
            g_boxes[b][s][1] = (int)ky0[s];
            g_boxes[b][s][2] = (int)kx1[s];
            g_boxes[b][s][3] = (int)ky1[s];
            out[OFF_COORDS + o * 4 + 0] = kx0[s];
            out[OFF_COORDS + o * 4 + 1] = ky0[s];
            out[OFF_COORDS + o * 4 + 2] = kx1[s];
            out[OFF_COORDS + o * 4 + 3] = ky1[s];
            out[OFF_PROB + o] = kprob[s];
            out[OFF_IDX + o] = (float)kidx[s];
        }
    }
}

// ---------------- bilinear crop-resize (pad emulated via bounds check) ----------------
// grid (224 rows, 3 channels, 48 boxes), block 224 (one ox per thread)
__global__ void crop_kernel(const float* __restrict__ xin, float* __restrict__ out) {
    const int ox = threadIdx.x;
    const int oy = blockIdx.x;
    const int c  = blockIdx.y;
    const int bs = blockIdx.z;           // b*6+s
    const int b  = bs / TOPN;
    const int s  = bs - b * TOPN;

    const int X0 = g_boxes[b][s][0], Y0 = g_boxes[b][s][1];
    const int X1 = g_boxes[b][s][2], Y1 = g_boxes[b][s][3];

    float ty = __fdiv_rn((float)oy, 223.0f);
    float sy = __fadd_rn((float)Y0, __fmul_rn(ty, (float)(Y1 - 1 - Y0)));
    int y0i = (int)floorf(sy);
    int y1i = min(y0i + 1, Y1 - 1);
    float wy = __fadd_rn(sy, -(float)y0i);

    float tx = __fdiv_rn((float)ox, 223.0f);
    float sx = __fadd_rn((float)X0, __fmul_rn(tx, (float)(X1 - 1 - X0)));
    int x0i = (int)floorf(sx);
    int x1i = min(x0i + 1, X1 - 1);
    float wx = __fadd_rn(sx, -(float)x0i);

    const float* img = xin + ((size_t)b * 3 + c) * 448 * 448;
    auto fetch = [&](int y, int x) -> float {
        y -= 224; x -= 224;
        if ((unsigned)y < 448u && (unsigned)x < 448u) return img[y * 448 + x];
        return 0.f;
    };
    float f00 = fetch(y0i, x0i), f01 = fetch(y0i, x1i);
    float f10 = fetch(y1i, x0i), f11 = fetch(y1i, x1i);

    float top = (1.f - wx) * f00 + wx * f01;
    float bot = (1.f - wx) * f10 + wx * f11;
    float v = (1.f - wy) * top + wy * bot;

    out[(((size_t)bs * 3 + c) * OUTP + oy) * OUTP + ox] = v;
}

// ---------------- launch ----------------
extern "C" void kernel_launch(void* const* d_in, const int* in_sizes, int n_in,
                              void* d_out, int out_size) {
    const float* x       = (const float*)d_in[0];
    const float* rpn     = (const float*)d_in[1];
    const float* anchors = (const float*)d_in[2];
    const float* wd1 = (const float*)d_in[3];
    const float* bd1 = (const float*)d_in[4];
    const float* wd2 = (const float*)d_in[5];
    const float* bd2 = (const float*)d_in[6];
    const float* wd3 = (const float*)d_in[7];
    const float* bd3 = (const float*)d_in[8];
    const float* wt1 = (const float*)d_in[9];
    const float* bt1 = (const float*)d_in[10];
    const float* wt2 = (const float*)d_in[11];
    const float* bt2 = (const float*)d_in[12];
    const float* wt3 = (const float*)d_in[13];
    const float* bt3 = (const float*)d_in[14];
    float* out = (float*)d_out;

    conv1_gemm<<<dim3(25, KSPL), 256>>>(rpn, wd1);
    reduce_relu_kernel<<<(128 * GN + 255) / 256, 256>>>(bd1);
    conv2_kernel<<<dim3(BATCH, 128), 64>>>(wd2, bd2);
    conv3_kernel<<<dim3(BATCH, 128), 32>>>(wd3, bd3);
    heads_kernel<<<dim3(BATCH, 7), 256>>>(wt1, bt1, wt2, bt2, wt3, bt3);
    nms_topk_kernel<<<BATCH, 512>>>(anchors, out);
    crop_kernel<<<dim3(OUTP, 3, BATCH * TOPN), OUTP>>>(x, out);
}

// round 4
// speedup vs baseline: 1.6714x; 1.6714x over previous
#include <cuda_runtime.h>
#include <cuda_bf16.h>
#include <math.h>

// ---------------- problem constants ----------------
#define BATCH 8
#define NA    1614          // anchors
#define TOPN  6
#define OUTP  224
// conv1: rpn (8,2048,14,14) -> d1 (8,128,14,14), 3x3 pad1
// GEMM: M=128, N=8*196=1568, K=2048*9=18432
#define GN    1568
#define GK    18432
#define KSPL  16
#define KPB   (GK / KSPL)   // 1152
#define NCH   (KPB / 16)    // 72 chunks of k=16

#define C2S   16            // conv2 ic-splits (8 ic each)
#define C3S   16            // conv3 ic-splits (8 ic each)

// output layout (flattened tuple, float32)
#define OFF_COORDS 7225344  // 48*3*224*224
#define OFF_PROB   7225536
#define OFF_IDX    7225584

// ---------------- scratch (device globals; no allocations allowed) ----------------
__device__ float g_part[KSPL][128][GN];     // conv1 K-split partials (~12.8MB)
__device__ float g_d1[BATCH][128][196];     // post-relu
__device__ float g_d2[BATCH][128][49];
__device__ float g_d3[BATCH][128][16];
__device__ float g_p2[C2S][BATCH][128][49]; // conv2 partials
__device__ float g_p3[C3S][BATCH][128][16]; // conv3 partials
__device__ float g_scores[BATCH][NA];
__device__ int   g_boxes[BATCH][TOPN][4];   // x0,y0,x1,y1 (ints, padded coords)

// ---------------- conv1 as implicit GEMM with K-split ----------------
// grid (25 n-tiles, 16 k-splits), 256 threads. C tile 128x64, thread tile 8x4.
// Single-sync double-buffered smem pipeline.
__global__ __launch_bounds__(256) void conv1_gemm(const float* __restrict__ rpn,
                                                  const float* __restrict__ wd1) {
    __shared__ float As[2][16][132];   // [buf][k][oc]
    __shared__ float Bs[2][16][64];    // [buf][k][px]

    const int t = threadIdx.x;
    const int n_base = blockIdx.x * 64;
    const int ks = blockIdx.y;

    // ---- B (im2col) per-thread invariants ----
    const int pn = t & 63;
    const int nn = n_base + pn;
    const bool nvalid = (nn < GN);
    const int nc = nvalid ? nn : 0;
    const int bb = nc / 196;
    const int pp = nc % 196;
    const int oy = pp / 14, ox = pp % 14;
    const int kk_b0 = t >> 6;                 // 0..3
    int ic[4], t9[4];
#pragma unroll
    for (int i = 0; i < 4; ++i) {
        int k = ks * KPB + kk_b0 + 4 * i;
        ic[i] = k / 9; t9[i] = k % 9;
    }
    const float* rbase = rpn + (size_t)bb * 2048 * 196;

    // ---- A per-thread invariants: wd1 viewed as [128][18432] ----
    const int kkA = (t & 3) * 4;
    const int ocA = t >> 2;                    // 0..63 (second row = +64)
    const float* pA0 = wd1 + (size_t)ocA * GK + ks * KPB + kkA;
    const float* pA1 = pA0 + (size_t)64 * GK;

    const int tm = t >> 4;     // 0..15 -> oc block of 8
    const int tn = t & 15;     // 0..15 -> px block of 4

    float acc[8][4];
#pragma unroll
    for (int r = 0; r < 8; ++r)
#pragma unroll
        for (int c = 0; c < 4; ++c) acc[r][c] = 0.f;

    float4 ra0, ra1;
    float rb[4];

    auto fetch = [&]() {
        ra0 = *(const float4*)pA0;
        ra1 = *(const float4*)pA1;
        pA0 += 16; pA1 += 16;
#pragma unroll
        for (int i = 0; i < 4; ++i) {
            int ky = t9[i] / 3, kx = t9[i] - 3 * (t9[i] / 3);
            int iy = oy + ky - 1, ix = ox + kx - 1;
            bool inb = nvalid && ((unsigned)iy < 14u) && ((unsigned)ix < 14u);
            rb[i] = inb ? rbase[ic[i] * 196 + iy * 14 + ix] : 0.f;
            // advance by 16 for next chunk (16 mod 9 = 7)
            t9[i] += 7; ic[i] += 1;
            if (t9[i] >= 9) { t9[i] -= 9; ic[i] += 1; }
        }
    };
    auto store = [&](int buf) {
        As[buf][kkA + 0][ocA] = ra0.x; As[buf][kkA + 1][ocA] = ra0.y;
        As[buf][kkA + 2][ocA] = ra0.z; As[buf][kkA + 3][ocA] = ra0.w;
        As[buf][kkA + 0][ocA + 64] = ra1.x; As[buf][kkA + 1][ocA + 64] = ra1.y;
        As[buf][kkA + 2][ocA + 64] = ra1.z; As[buf][kkA + 3][ocA + 64] = ra1.w;
#pragma unroll
        for (int i = 0; i < 4; ++i) Bs[buf][kk_b0 + 4 * i][pn] = rb[i];
    };

    fetch();
    store(0);
    __syncthreads();

    for (int ch = 0; ch < NCH; ++ch) {
        const int cur = ch & 1;
        const bool more = (ch + 1 < NCH);
        if (more) fetch();          // global loads overlap compute below

#pragma unroll
        for (int kk = 0; kk < 16; ++kk) {
            float4 af0 = *(const float4*)&As[cur][kk][tm * 8];
            float4 af1 = *(const float4*)&As[cur][kk][tm * 8 + 4];
            float4 bf  = *(const float4*)&Bs[cur][kk][tn * 4];
            float av[8] = {af0.x, af0.y, af0.z, af0.w, af1.x, af1.y, af1.z, af1.w};
            float bw[4] = {bf.x, bf.y, bf.z, bf.w};
#pragma unroll
            for (int r = 0; r < 8; ++r)
#pragma unroll
                for (int c = 0; c < 4; ++c) acc[r][c] += av[r] * bw[c];
        }

        if (more) store(cur ^ 1);   // writes go to the other buffer: no hazard
        __syncthreads();
    }

    const int n0 = n_base + tn * 4;
    if (n0 < GN) {
#pragma unroll
        for (int r = 0; r < 8; ++r) {
            int oc = tm * 8 + r;
            float4 v = make_float4(acc[r][0], acc[r][1], acc[r][2], acc[r][3]);
            *(float4*)&g_part[ks][oc][n0] = v;
        }
    }
}

// sum K-split partials + bias + relu -> g_d1
__global__ void reduce_relu_kernel(const float* __restrict__ bd1) {
    int i = blockIdx.x * 256 + threadIdx.x;
    if (i >= 128 * GN) return;
    int oc = i / GN, n = i - oc * GN;
    float s = bd1[oc];
#pragma unroll
    for (int ks = 0; ks < KSPL; ++ks) s += g_part[ks][oc][n];
    int b = n / 196, p = n - b * 196;
    g_d1[b][oc][p] = fmaxf(s, 0.f);
}

// ---------------- conv2: d1(14x14) -> d2(7x7), 3x3 stride2 pad1 ----------------
// grid (8 b, 16 ic-splits of 8 ic), 392 threads: px = t%49, ocg = t/49 (8 groups of 16 oc)
__global__ __launch_bounds__(392) void conv2_part(const float* __restrict__ wd2) {
    __shared__ float ds[8][196];
    __shared__ float ws[8][128][9];
    const int b = blockIdx.x, sp = blockIdx.y;
    const int t = threadIdx.x;

    for (int i = t; i < 8 * 196; i += 392) {
        int ic = i / 196, p = i - ic * 196;
        ds[ic][p] = g_d1[b][sp * 8 + ic][p];
    }
    for (int i = t; i < 8 * 128 * 9; i += 392) {
        int ic = i / (128 * 9);
        int r = i - ic * (128 * 9);
        int oc = r / 9, k = r - oc * 9;
        ws[ic][oc][k] = wd2[(size_t)oc * 1152 + (sp * 8 + ic) * 9 + k];
    }
    __syncthreads();

    const int p = t % 49;
    const int g = t / 49;          // 0..7
    const int oy = p / 7, ox = p - 7 * (p / 7);

    float acc[16];
#pragma unroll
    for (int r = 0; r < 16; ++r) acc[r] = 0.f;

    for (int ic = 0; ic < 8; ++ic) {
        float d[9];
#pragma unroll
        for (int ky = 0; ky < 3; ++ky)
#pragma unroll
            for (int kx = 0; kx < 3; ++kx) {
                int iy = 2 * oy - 1 + ky, ix = 2 * ox - 1 + kx;
                bool inb = ((unsigned)iy < 14u) && ((unsigned)ix < 14u);
                d[ky * 3 + kx] = inb ? ds[ic][iy * 14 + ix] : 0.f;
            }
#pragma unroll
        for (int r = 0; r < 16; ++r) {
            const float* w = &ws[ic][g * 16 + r][0];
            float a = acc[r];
#pragma unroll
            for (int k = 0; k < 9; ++k) a += w[k] * d[k];
            acc[r] = a;
        }
    }
#pragma unroll
    for (int r = 0; r < 16; ++r) g_p2[sp][b][g * 16 + r][p] = acc[r];
}

__global__ void conv2_reduce(const float* __restrict__ bd2) {
    int i = blockIdx.x * 256 + threadIdx.x;
    if (i >= BATCH * 128 * 49) return;
    int b = i / (128 * 49);
    int r = i - b * (128 * 49);
    int oc = r / 49, p = r - oc * 49;
    float s = bd2[oc];
#pragma unroll
    for (int sp = 0; sp < C2S; ++sp) s += g_p2[sp][b][oc][p];
    g_d2[b][oc][p] = fmaxf(s, 0.f);
}

// ---------------- conv3: d2(7x7) -> d3(4x4), 3x3 stride2 pad1 ----------------
// grid (8 b, 16 ic-splits of 8 ic), 128 threads: px = t%16, ocg = t/16 (8 groups of 16 oc)
__global__ __launch_bounds__(128) void conv3_part(const float* __restrict__ wd3) {
    __shared__ float ds[8][49];
    __shared__ float ws[8][128][9];
    const int b = blockIdx.x, sp = blockIdx.y;
    const int t = threadIdx.x;

    for (int i = t; i < 8 * 49; i += 128) {
        int ic = i / 49, p = i - ic * 49;
        ds[ic][p] = g_d2[b][sp * 8 + ic][p];
    }
    for (int i = t; i < 8 * 128 * 9; i += 128) {
        int ic = i / (128 * 9);
        int r = i - ic * (128 * 9);
        int oc = r / 9, k = r - oc * 9;
        ws[ic][oc][k] = wd3[(size_t)oc * 1152 + (sp * 8 + ic) * 9 + k];
    }
    __syncthreads();

    const int p = t & 15;
    const int g = t >> 4;         // 0..7
    const int oy = p >> 2, ox = p & 3;

    float acc[16];
#pragma unroll
    for (int r = 0; r < 16; ++r) acc[r] = 0.f;

    for (int ic = 0; ic < 8; ++ic) {
        float d[9];
#pragma unroll
        for (int ky = 0; ky < 3; ++ky)
#pragma unroll
            for (int kx = 0; kx < 3; ++kx) {
                int iy = 2 * oy - 1 + ky, ix = 2 * ox - 1 + kx;
                bool inb = ((unsigned)iy < 7u) && ((unsigned)ix < 7u);
                d[ky * 3 + kx] = inb ? ds[ic][iy * 7 + ix] : 0.f;
            }
#pragma unroll
        for (int r = 0; r < 16; ++r) {
            const float* w = &ws[ic][g * 16 + r][0];
            float a = acc[r];
#pragma unroll
            for (int k = 0; k < 9; ++k) a += w[k] * d[k];
            acc[r] = a;
        }
    }
#pragma unroll
    for (int r = 0; r < 16; ++r) g_p3[sp][b][g * 16 + r][p] = acc[r];
}

__global__ void conv3_reduce(const float* __restrict__ bd3) {
    int i = blockIdx.x * 256 + threadIdx.x;
    if (i >= BATCH * 128 * 16) return;
    int b = i / (128 * 16);
    int r = i - b * (128 * 16);
    int oc = r / 16, p = r & 15;
    float s = bd3[oc];
#pragma unroll
    for (int sp = 0; sp < C3S; ++sp) s += g_p3[sp][b][oc][p];
    g_d3[b][oc][p] = fmaxf(s, 0.f);
}

// ---------------- 1x1 score heads -> g_scores ----------------
__global__ void heads_kernel(const float* __restrict__ wt1, const float* __restrict__ bt1,
                             const float* __restrict__ wt2, const float* __restrict__ bt2,
                             const float* __restrict__ wt3, const float* __restrict__ bt3) {
    int b = blockIdx.x;
    int a = blockIdx.y * 256 + threadIdx.x;
    if (a >= NA) return;
    float acc;
    if (a < 1176) {
        int c = a / 196, p = a - c * 196;
        acc = bt1[c];
        const float* w = wt1 + c * 128;
        for (int ic = 0; ic < 128; ++ic) acc += g_d1[b][ic][p] * w[ic];
    } else if (a < 1470) {
        int a2 = a - 1176;
        int c = a2 / 49, p = a2 - c * 49;
        acc = bt2[c];
        const float* w = wt2 + c * 128;
        for (int ic = 0; ic < 128; ++ic) acc += g_d2[b][ic][p] * w[ic];
    } else {
        int a3 = a - 1470;
        int c = a3 / 16, p = a3 & 15;
        acc = bt3[c];
        const float* w = wt3 + c * 128;
        for (int ic = 0; ic < 128; ++ic) acc += g_d3[b][ic][p] * w[ic];
    }
    g_scores[b][a] = acc;
}

// ---------------- NMS + top-6 per batch ----------------
// Key: (sortable(score) << 32) | ~idx  -> descending sort = score desc, idx asc (stable).
// Greedy NMS only needs comparison against kept-so-far; stop at 6 kept.
__global__ __launch_bounds__(1024) void nms_topk_kernel(const float* __restrict__ anchors,
                                                        float* __restrict__ out) {
    __shared__ unsigned long long key[2048];
    const int b = blockIdx.x;
    const int tid = threadIdx.x;

    for (int a = tid; a < 2048; a += 1024) {
        unsigned long long k = 0ull;
        if (a < NA) {
            unsigned u = __float_as_uint(g_scores[b][a]);
            unsigned us = (u & 0x80000000u) ? ~u : (u | 0x80000000u);
            k = ((unsigned long long)us << 32) | (unsigned)(~(unsigned)a);
        }
        key[a] = k;
    }

    for (int kk = 2; kk <= 2048; kk <<= 1) {
        for (int j = kk >> 1; j > 0; j >>= 1) {
            __syncthreads();
            for (int i = tid; i < 2048; i += 1024) {
                int ixj = i ^ j;
                if (ixj > i) {
                    unsigned long long x = key[i], y = key[ixj];
                    bool desc = ((i & kk) == 0);
                    if (desc ? (x < y) : (x > y)) { key[i] = y; key[ixj] = x; }
                }
            }
        }
    }
    __syncthreads();

    if (tid == 0) {
        float ky0[TOPN], kx0[TOPN], ky1[TOPN], kx1[TOPN], karea[TOPN], kprob[TOPN];
        int kidx[TOPN];
        int nk = 0;
        for (int r = 0; r < NA && nk < TOPN; ++r) {
            unsigned long long k = key[r];
            int idx = (int)(~(unsigned)k);
            if (idx >= NA) break;
            float y0 = anchors[idx * 4 + 0], x0 = anchors[idx * 4 + 1];
            float y1 = anchors[idx * 4 + 2], x1 = anchors[idx * 4 + 3];
            float area = (y1 - y0) * (x1 - x0);
            bool sup = false;
            for (int s = 0; s < nk; ++s) {
                float ih = fminf(y1, ky1[s]) - fmaxf(y0, ky0[s]); if (ih < 0.f) ih = 0.f;
                float iw = fminf(x1, kx1[s]) - fmaxf(x0, kx0[s]); if (iw < 0.f) iw = 0.f;
                float inter = ih * iw;
                if (inter > 0.25f * (area + karea[s] - inter)) { sup = true; break; }
            }
            if (!sup) {
                unsigned us = (unsigned)(k >> 32);
                unsigned u = (us & 0x80000000u) ? (us ^ 0x80000000u) : ~us;
                ky0[nk] = y0; kx0[nk] = x0; ky1[nk] = y1; kx1[nk] = x1;
                karea[nk] = area; kidx[nk] = idx; kprob[nk] = __uint_as_float(u);
                ++nk;
            }
        }
        int fi = 0;
        while (nk < TOPN) {
            bool used = false;
            for (int s = 0; s < nk; ++s) if (kidx[s] == fi) used = true;
            if (!used) {
                ky0[nk] = anchors[fi * 4 + 0]; kx0[nk] = anchors[fi * 4 + 1];
                ky1[nk] = anchors[fi * 4 + 2]; kx1[nk] = anchors[fi * 4 + 3];
                karea[nk] = 0.f; kidx[nk] = fi; kprob[nk] = -INFINITY;
                ++nk;
            }
            ++fi;
        }
        for (int s = 0; s < TOPN; ++s) {
            int o = b * TOPN + s;
            g_boxes[b][s][0] = (int)kx0[s];
            g_boxes[b][s][1] = (int)ky0[s];
            g_boxes[b][s][2] = (int)kx1[s];
            g_boxes[b][s][3] = (int)ky1[s];
            out[OFF_COORDS + o * 4 + 0] = kx0[s];
            out[OFF_COORDS + o * 4 + 1] = ky0[s];
            out[OFF_COORDS + o * 4 + 2] = kx1[s];
            out[OFF_COORDS + o * 4 + 3] = ky1[s];
            out[OFF_PROB + o] = kprob[s];
            out[OFF_IDX + o] = (float)kidx[s];
        }
    }
}

// ---------------- bilinear crop-resize (pad emulated via bounds check) ----------------
__global__ void crop_kernel(const float* __restrict__ xin, float* __restrict__ out) {
    const int ox = threadIdx.x;
    const int oy = blockIdx.x;
    const int c  = blockIdx.y;
    const int bs = blockIdx.z;           // b*6+s
    const int b  = bs / TOPN;
    const int s  = bs - b * TOPN;

    const int X0 = g_boxes[b][s][0], Y0 = g_boxes[b][s][1];
    const int X1 = g_boxes[b][s][2], Y1 = g_boxes[b][s][3];

    float ty = __fdiv_rn((float)oy, 223.0f);
    float sy = __fadd_rn((float)Y0, __fmul_rn(ty, (float)(Y1 - 1 - Y0)));
    int y0i = (int)floorf(sy);
    int y1i = min(y0i + 1, Y1 - 1);
    float wy = __fadd_rn(sy, -(float)y0i);

    float tx = __fdiv_rn((float)ox, 223.0f);
    float sx = __fadd_rn((float)X0, __fmul_rn(tx, (float)(X1 - 1 - X0)));
    int x0i = (int)floorf(sx);
    int x1i = min(x0i + 1, X1 - 1);
    float wx = __fadd_rn(sx, -(float)x0i);

    const float* img = xin + ((size_t)b * 3 + c) * 448 * 448;
    auto fetch = [&](int y, int x) -> float {
        y -= 224; x -= 224;
        if ((unsigned)y < 448u && (unsigned)x < 448u) return img[y * 448 + x];
        return 0.f;
    };
    float f00 = fetch(y0i, x0i), f01 = fetch(y0i, x1i);
    float f10 = fetch(y1i, x0i), f11 = fetch(y1i, x1i);

    float top = (1.f - wx) * f00 + wx * f01;
    float bot = (1.f - wx) * f10 + wx * f11;
    float v = (1.f - wy) * top + wy * bot;

    out[(((size_t)bs * 3 + c) * OUTP + oy) * OUTP + ox] = v;
}

// ---------------- launch ----------------
extern "C" void kernel_launch(void* const* d_in, const int* in_sizes, int n_in,
                              void* d_out, int out_size) {
    const float* x       = (const float*)d_in[0];
    const float* rpn     = (const float*)d_in[1];
    const float* anchors = (const float*)d_in[2];
    const float* wd1 = (const float*)d_in[3];
    const float* bd1 = (const float*)d_in[4];
    const float* wd2 = (const float*)d_in[5];
    const float* bd2 = (const float*)d_in[6];
    const float* wd3 = (const float*)d_in[7];
    const float* bd3 = (const float*)d_in[8];
    const float* wt1 = (const float*)d_in[9];
    const float* bt1 = (const float*)d_in[10];
    const float* wt2 = (const float*)d_in[11];
    const float* bt2 = (const float*)d_in[12];
    const float* wt3 = (const float*)d_in[13];
    const float* bt3 = (const float*)d_in[14];
    float* out = (float*)d_out;

    conv1_gemm<<<dim3(25, KSPL), 256>>>(rpn, wd1);
    reduce_relu_kernel<<<(128 * GN + 255) / 256, 256>>>(bd1);
    conv2_part<<<dim3(BATCH, C2S), 392>>>(wd2);
    conv2_reduce<<<(BATCH * 128 * 49 + 255) / 256, 256>>>(bd2);
    conv3_part<<<dim3(BATCH, C3S), 128>>>(wd3);
    conv3_reduce<<<(BATCH * 128 * 16 + 255) / 256, 256>>>(bd3);
    heads_kernel<<<dim3(BATCH, 7), 256>>>(wt1, bt1, wt2, bt2, wt3, bt3);
    nms_topk_kernel<<<BATCH, 1024>>>(anchors, out);
    crop_kernel<<<dim3(OUTP, 3, BATCH * TOPN), OUTP>>>(x, out);
}

// round 6
// speedup vs baseline: 2.1266x; 1.2724x over previous
#include <cuda_runtime.h>
#include <cuda_bf16.h>
#include <mma.h>
#include <math.h>
#include <stdint.h>

using namespace nvcuda;

// ---------------- problem constants ----------------
#define BATCH 8
#define NA    1614
#define TOPN  6
#define OUTP  224
#define GN    1568              // 8*196 px
#define GNP   1664              // padded N (13 tiles * 128)
#define GK    18432             // 2048*9
#define KS1   32                // conv1 K-splits
#define NCH1  36                // chunks of k=16 per split (18432/32/16)
#define C2S   16
#define C3S   16

#define OFF_COORDS 7225344
#define OFF_PROB   7225536
#define OFF_IDX    7225584

// smem element offsets (bf16 elems), ldm 24 (16 used + 8 pad)
#define AH_O  0
#define AL_O  3072
#define BH_O  6144
#define BL_O  9216
#define BUFS  12288
#define DYNSMEM (2 * BUFS * 2)      // 49152 bytes (== default 48KB limit)

// ---------------- scratch globals ----------------
__device__ __nv_bfloat16 g_wAh[128 * 9 * 2048];   // weights [oc][t9][ic] hi
__device__ __nv_bfloat16 g_wAl[128 * 9 * 2048];   // lo
__device__ __nv_bfloat16 g_rTh[8 * 196 * 2048];   // rpn NHWC [b][p][ic] hi
__device__ __nv_bfloat16 g_rTl[8 * 196 * 2048];   // lo
__device__ float g_part[KS1][128][GNP];
__device__ float g_d1[BATCH][128][196];
__device__ float g_d2[BATCH][128][49];
__device__ float g_d3[BATCH][128][16];
__device__ float g_p2[C2S][BATCH][128][49];
__device__ float g_p3[C3S][BATCH][128][16];
__device__ float g_scores[BATCH][NA];
__device__ int   g_boxes[BATCH][TOPN][4];

// ---------------- weight prep: wd1[oc][ic*9+t9] -> g_wA{h,l}[oc][t9][ic] ----------------
__global__ __launch_bounds__(256) void prep_w(const float* __restrict__ wd1) {
    __shared__ float w[2304];
    const int oc = blockIdx.x;
    const int ic0 = blockIdx.y * 256;
    const float* src = wd1 + (size_t)oc * GK + (size_t)ic0 * 9;
    for (int i = threadIdx.x; i < 2304; i += 256) w[i] = src[i];
    __syncthreads();
    for (int i = threadIdx.x; i < 2304; i += 256) {
        int t9 = i >> 8, ic = i & 255;
        float a = w[ic * 9 + t9];
        __nv_bfloat16 hi = __float2bfloat16(a);
        __nv_bfloat16 lo = __float2bfloat16(a - __bfloat162float(hi));
        int o = (oc * 9 + t9) * 2048 + ic0 + ic;
        g_wAh[o] = hi; g_wAl[o] = lo;
    }
}

// ---------------- rpn prep: (b,ic,p) fp32 -> NHWC bf16 hi/lo ----------------
__global__ __launch_bounds__(256) void prep_rpn(const float* __restrict__ rpn) {
    __shared__ float sm_[32][197];
    const int b = blockIdx.x;
    const int ic0 = blockIdx.y * 32;
    const float* src = rpn + ((size_t)b * 2048 + ic0) * 196;
    for (int i = threadIdx.x; i < 32 * 196; i += 256) {
        int ic = i / 196, p = i - ic * 196;
        sm_[ic][p] = src[ic * 196 + p];
    }
    __syncthreads();
    for (int i = threadIdx.x; i < 32 * 196; i += 256) {
        int p = i >> 5, ic = i & 31;
        float a = sm_[ic][p];
        __nv_bfloat16 hi = __float2bfloat16(a);
        __nv_bfloat16 lo = __float2bfloat16(a - __bfloat162float(hi));
        int o = (b * 196 + p) * 2048 + ic0 + ic;
        g_rTh[o] = hi; g_rTl[o] = lo;
    }
}

// ---------------- conv1 via wmma bf16 hi/lo split ----------------
// grid (13 n-tiles, 32 k-splits), 256 thr. CTA tile M=128 oc x N=128 px, K chunk 16.
// Warp grid 2x4: warp tile 64x32 = 4x2 fragments of 16x16. 3 split-terms per chunk.
__global__ __launch_bounds__(256) void conv1_wmma() {
    extern __shared__ __nv_bfloat16 sm[];
    const int t = threadIdx.x;
    const int warp = t >> 5;
    const int nbase = blockIdx.x * 128;
    const int ks = blockIdx.y;
    const int wm = (warp >> 2) * 64;
    const int wn = (warp & 3) * 32;

    wmma::fragment<wmma::accumulator, 16, 16, 16, float> acc[4][2];
#pragma unroll
    for (int m = 0; m < 4; ++m)
#pragma unroll
        for (int n = 0; n < 2; ++n) wmma::fill_fragment(acc[m][n], 0.f);

    // per-thread load invariants: idx = i*256 + t, i in 0..1 (512 16B loads each op)
    // arr = idx>>8, row = (idx>>1)&127, half = idx&1
    int b_b[2], b_oy[2], b_ox[2]; bool b_v[2];
    int l_arr[2], l_row[2], l_half[2];
#pragma unroll
    for (int i = 0; i < 2; ++i) {
        int idx = i * 256 + t;
        l_arr[i] = idx >> 8; l_row[i] = (idx >> 1) & 127; l_half[i] = idx & 1;
        int px = nbase + l_row[i];
        bool v = px < GN;
        int pc = v ? px : 0;
        int bb = pc / 196, pp = pc - bb * 196;
        b_b[i] = bb; b_oy[i] = pp / 14; b_ox[i] = pp - 14 * (pp / 14); b_v[i] = v;
    }

    uint4 ra[2], rb[2];
    auto fetch = [&](int ch) {
        const int g = ks * NCH1 + ch;
        const int t9 = g >> 7;
        const int icb = (g & 127) << 4;
        const int ky = t9 / 3, kx = t9 - 3 * (t9 / 3);
#pragma unroll
        for (int i = 0; i < 2; ++i) {
            const __nv_bfloat16* srcA = (l_arr[i] ? g_wAl : g_wAh) +
                ((l_row[i] * 9 + t9) << 11) + icb + l_half[i] * 8;
            ra[i] = *(const uint4*)srcA;
            int iy = b_oy[i] + ky - 1, ix = b_ox[i] + kx - 1;
            bool inb = b_v[i] && ((unsigned)iy < 14u) && ((unsigned)ix < 14u);
            if (inb) {
                const __nv_bfloat16* srcB = (l_arr[i] ? g_rTl : g_rTh) +
                    (((b_b[i] * 196 + iy * 14 + ix)) << 11) + icb + l_half[i] * 8;
                rb[i] = *(const uint4*)srcB;
            } else {
                rb[i] = make_uint4(0, 0, 0, 0);
            }
        }
    };
    auto store = [&](int buf) {
        __nv_bfloat16* bp = sm + buf * BUFS;
#pragma unroll
        for (int i = 0; i < 2; ++i) {
            *(uint4*)(bp + (l_arr[i] ? AL_O : AH_O) + l_row[i] * 24 + l_half[i] * 8) = ra[i];
            *(uint4*)(bp + (l_arr[i] ? BL_O : BH_O) + l_row[i] * 24 + l_half[i] * 8) = rb[i];
        }
    };

    fetch(0);
    store(0);
    __syncthreads();

    for (int ch = 0; ch < NCH1; ++ch) {
        const int cur = ch & 1;
        const bool more = (ch + 1 < NCH1);
        if (more) fetch(ch + 1);

        const __nv_bfloat16* bp = sm + cur * BUFS;
#pragma unroll
        for (int c = 0; c < 3; ++c) {
            const __nv_bfloat16* Ab = bp + (c == 2 ? AL_O : AH_O);
            const __nv_bfloat16* Bb = bp + (c == 1 ? BL_O : BH_O);
            wmma::fragment<wmma::matrix_b, 16, 16, 16, __nv_bfloat16, wmma::col_major> fb[2];
#pragma unroll
            for (int n = 0; n < 2; ++n)
                wmma::load_matrix_sync(fb[n], Bb + (wn + n * 16) * 24, 24);
#pragma unroll
            for (int m = 0; m < 4; ++m) {
                wmma::fragment<wmma::matrix_a, 16, 16, 16, __nv_bfloat16, wmma::row_major> fa;
                wmma::load_matrix_sync(fa, Ab + (wm + m * 16) * 24, 24);
                wmma::mma_sync(acc[m][0], fa, fb[0], acc[m][0]);
                wmma::mma_sync(acc[m][1], fa, fb[1], acc[m][1]);
            }
        }

        if (more) store(cur ^ 1);
        __syncthreads();
    }

    float* base = &g_part[ks][0][0];
#pragma unroll
    for (int m = 0; m < 4; ++m)
#pragma unroll
        for (int n = 0; n < 2; ++n)
            wmma::store_matrix_sync(base + (size_t)(wm + m * 16) * GNP + nbase + wn + n * 16,
                                    acc[m][n], GNP, wmma::mem_row_major);
}

// sum K-split partials + bias + relu -> g_d1
__global__ void reduce_relu_kernel(const float* __restrict__ bd1) {
    int i = blockIdx.x * 256 + threadIdx.x;
    if (i >= 128 * GN) return;
    int oc = i / GN, n = i - oc * GN;
    float s = bd1[oc];
#pragma unroll
    for (int ks = 0; ks < KS1; ++ks) s += g_part[ks][oc][n];
    int b = n / 196, p = n - b * 196;
    g_d1[b][oc][p] = fmaxf(s, 0.f);
}

// ---------------- conv2 ----------------
__global__ __launch_bounds__(392) void conv2_part(const float* __restrict__ wd2) {
    __shared__ float ds[8][196];
    __shared__ float ws[8][128][9];
    const int b = blockIdx.x, sp = blockIdx.y;
    const int t = threadIdx.x;
    for (int i = t; i < 8 * 196; i += 392) {
        int ic = i / 196, p = i - ic * 196;
        ds[ic][p] = g_d1[b][sp * 8 + ic][p];
    }
    for (int i = t; i < 8 * 128 * 9; i += 392) {
        int ic = i / (128 * 9);
        int r = i - ic * (128 * 9);
        int oc = r / 9, k = r - oc * 9;
        ws[ic][oc][k] = wd2[(size_t)oc * 1152 + (sp * 8 + ic) * 9 + k];
    }
    __syncthreads();
    const int p = t % 49;
    const int g = t / 49;
    const int oy = p / 7, ox = p - 7 * (p / 7);
    float acc[16];
#pragma unroll
    for (int r = 0; r < 16; ++r) acc[r] = 0.f;
    for (int ic = 0; ic < 8; ++ic) {
        float d[9];
#pragma unroll
        for (int ky = 0; ky < 3; ++ky)
#pragma unroll
            for (int kx = 0; kx < 3; ++kx) {
                int iy = 2 * oy - 1 + ky, ix = 2 * ox - 1 + kx;
                bool inb = ((unsigned)iy < 14u) && ((unsigned)ix < 14u);
                d[ky * 3 + kx] = inb ? ds[ic][iy * 14 + ix] : 0.f;
            }
#pragma unroll
        for (int r = 0; r < 16; ++r) {
            const float* w = &ws[ic][g * 16 + r][0];
            float a = acc[r];
#pragma unroll
            for (int k = 0; k < 9; ++k) a += w[k] * d[k];
            acc[r] = a;
        }
    }
#pragma unroll
    for (int r = 0; r < 16; ++r) g_p2[sp][b][g * 16 + r][p] = acc[r];
}

__global__ void conv2_reduce(const float* __restrict__ bd2) {
    int i = blockIdx.x * 256 + threadIdx.x;
    if (i >= BATCH * 128 * 49) return;
    int b = i / (128 * 49);
    int r = i - b * (128 * 49);
    int oc = r / 49, p = r - oc * 49;
    float s = bd2[oc];
#pragma unroll
    for (int sp = 0; sp < C2S; ++sp) s += g_p2[sp][b][oc][p];
    g_d2[b][oc][p] = fmaxf(s, 0.f);
}

// ---------------- conv3 ----------------
__global__ __launch_bounds__(128) void conv3_part(const float* __restrict__ wd3) {
    __shared__ float ds[8][49];
    __shared__ float ws[8][128][9];
    const int b = blockIdx.x, sp = blockIdx.y;
    const int t = threadIdx.x;
    for (int i = t; i < 8 * 49; i += 128) {
        int ic = i / 49, p = i - ic * 49;
        ds[ic][p] = g_d2[b][sp * 8 + ic][p];
    }
    for (int i = t; i < 8 * 128 * 9; i += 128) {
        int ic = i / (128 * 9);
        int r = i - ic * (128 * 9);
        int oc = r / 9, k = r - oc * 9;
        ws[ic][oc][k] = wd3[(size_t)oc * 1152 + (sp * 8 + ic) * 9 + k];
    }
    __syncthreads();
    const int p = t & 15;
    const int g = t >> 4;
    const int oy = p >> 2, ox = p & 3;
    float acc[16];
#pragma unroll
    for (int r = 0; r < 16; ++r) acc[r] = 0.f;
    for (int ic = 0; ic < 8; ++ic) {
        float d[9];
#pragma unroll
        for (int ky = 0; ky < 3; ++ky)
#pragma unroll
            for (int kx = 0; kx < 3; ++kx) {
                int iy = 2 * oy - 1 + ky, ix = 2 * ox - 1 + kx;
                bool inb = ((unsigned)iy < 7u) && ((unsigned)ix < 7u);
                d[ky * 3 + kx] = inb ? ds[ic][iy * 7 + ix] : 0.f;
            }
#pragma unroll
        for (int r = 0; r < 16; ++r) {
            const float* w = &ws[ic][g * 16 + r][0];
            float a = acc[r];
#pragma unroll
            for (int k = 0; k < 9; ++k) a += w[k] * d[k];
            acc[r] = a;
        }
    }
#pragma unroll
    for (int r = 0; r < 16; ++r) g_p3[sp][b][g * 16 + r][p] = acc[r];
}

__global__ void conv3_reduce(const float* __restrict__ bd3) {
    int i = blockIdx.x * 256 + threadIdx.x;
    if (i >= BATCH * 128 * 16) return;
    int b = i / (128 * 16);
    int r = i - b * (128 * 16);
    int oc = r / 16, p = r & 15;
    float s = bd3[oc];
#pragma unroll
    for (int sp = 0; sp < C3S; ++sp) s += g_p3[sp][b][oc][p];
    g_d3[b][oc][p] = fmaxf(s, 0.f);
}

// ---------------- heads ----------------
__global__ void heads_kernel(const float* __restrict__ wt1, const float* __restrict__ bt1,
                             const float* __restrict__ wt2, const float* __restrict__ bt2,
                             const float* __restrict__ wt3, const float* __restrict__ bt3) {
    int b = blockIdx.x;
    int a = blockIdx.y * 256 + threadIdx.x;
    if (a >= NA) return;
    float acc;
    if (a < 1176) {
        int c = a / 196, p = a - c * 196;
        acc = bt1[c];
        const float* w = wt1 + c * 128;
        for (int ic = 0; ic < 128; ++ic) acc += g_d1[b][ic][p] * w[ic];
    } else if (a < 1470) {
        int a2 = a - 1176;
        int c = a2 / 49, p = a2 - c * 49;
        acc = bt2[c];
        const float* w = wt2 + c * 128;
        for (int ic = 0; ic < 128; ++ic) acc += g_d2[b][ic][p] * w[ic];
    } else {
        int a3 = a - 1470;
        int c = a3 / 16, p = a3 & 15;
        acc = bt3[c];
        const float* w = wt3 + c * 128;
        for (int ic = 0; ic < 128; ++ic) acc += g_d3[b][ic][p] * w[ic];
    }
    g_scores[b][a] = acc;
}

// ---------------- NMS + top-6 ----------------
__global__ __launch_bounds__(1024) void nms_topk_kernel(const float* __restrict__ anchors,
                                                        float* __restrict__ out) {
    __shared__ unsigned long long key[2048];
    const int b = blockIdx.x;
    const int tid = threadIdx.x;

    for (int a = tid; a < 2048; a += 1024) {
        unsigned long long k = 0ull;
        if (a < NA) {
            unsigned u = __float_as_uint(g_scores[b][a]);
            unsigned us = (u & 0x80000000u) ? ~u : (u | 0x80000000u);
            k = ((unsigned long long)us << 32) | (unsigned)(~(unsigned)a);
        }
        key[a] = k;
    }
    for (int kk = 2; kk <= 2048; kk <<= 1) {
        for (int j = kk >> 1; j > 0; j >>= 1) {
            __syncthreads();
            for (int i = tid; i < 2048; i += 1024) {
                int ixj = i ^ j;
                if (ixj > i) {
                    unsigned long long x = key[i], y = key[ixj];
                    bool desc = ((i & kk) == 0);
                    if (desc ? (x < y) : (x > y)) { key[i] = y; key[ixj] = x; }
                }
            }
        }
    }
    __syncthreads();

    if (tid == 0) {
        float ky0[TOPN], kx0[TOPN], ky1[TOPN], kx1[TOPN], karea[TOPN], kprob[TOPN];
        int kidx[TOPN];
        int nk = 0;
        for (int r = 0; r < NA && nk < TOPN; ++r) {
            unsigned long long k = key[r];
            int idx = (int)(~(unsigned)k);
            if (idx >= NA) break;
            float y0 = anchors[idx * 4 + 0], x0 = anchors[idx * 4 + 1];
            float y1 = anchors[idx * 4 + 2], x1 = anchors[idx * 4 + 3];
            float area = (y1 - y0) * (x1 - x0);
            bool sup = false;
            for (int s = 0; s < nk; ++s) {
                float ih = fminf(y1, ky1[s]) - fmaxf(y0, ky0[s]); if (ih < 0.f) ih = 0.f;
                float iw = fminf(x1, kx1[s]) - fmaxf(x0, kx0[s]); if (iw < 0.f) iw = 0.f;
                float inter = ih * iw;
                if (inter > 0.25f * (area + karea[s] - inter)) { sup = true; break; }
            }
            if (!sup) {
                unsigned us = (unsigned)(k >> 32);
                unsigned u = (us & 0x80000000u) ? (us ^ 0x80000000u) : ~us;
                ky0[nk] = y0; kx0[nk] = x0; ky1[nk] = y1; kx1[nk] = x1;
                karea[nk] = area; kidx[nk] = idx; kprob[nk] = __uint_as_float(u);
                ++nk;
            }
        }
        int fi = 0;
        while (nk < TOPN) {
            bool used = false;
            for (int s = 0; s < nk; ++s) if (kidx[s] == fi) used = true;
            if (!used) {
                ky0[nk] = anchors[fi * 4 + 0]; kx0[nk] = anchors[fi * 4 + 1];
                ky1[nk] = anchors[fi * 4 + 2]; kx1[nk] = anchors[fi * 4 + 3];
                karea[nk] = 0.f; kidx[nk] = fi; kprob[nk] = -INFINITY;
                ++nk;
            }
            ++fi;
        }
        for (int s = 0; s < TOPN; ++s) {
            int o = b * TOPN + s;
            g_boxes[b][s][0] = (int)kx0[s];
            g_boxes[b][s][1] = (int)ky0[s];
            g_boxes[b][s][2] = (int)kx1[s];
            g_boxes[b][s][3] = (int)ky1[s];
            out[OFF_COORDS + o * 4 + 0] = kx0[s];
            out[OFF_COORDS + o * 4 + 1] = ky0[s];
            out[OFF_COORDS + o * 4 + 2] = kx1[s];
            out[OFF_COORDS + o * 4 + 3] = ky1[s];
            out[OFF_PROB + o] = kprob[s];
            out[OFF_IDX + o] = (float)kidx[s];
        }
    }
}

// ---------------- crop-resize ----------------
__global__ void crop_kernel(const float* __restrict__ xin, float* __restrict__ out) {
    const int ox = threadIdx.x;
    const int oy = blockIdx.x;
    const int c  = blockIdx.y;
    const int bs = blockIdx.z;
    const int b  = bs / TOPN;
    const int s  = bs - b * TOPN;

    const int X0 = g_boxes[b][s][0], Y0 = g_boxes[b][s][1];
    const int X1 = g_boxes[b][s][2], Y1 = g_boxes[b][s][3];

    float ty = __fdiv_rn((float)oy, 223.0f);
    float sy = __fadd_rn((float)Y0, __fmul_rn(ty, (float)(Y1 - 1 - Y0)));
    int y0i = (int)floorf(sy);
    int y1i = min(y0i + 1, Y1 - 1);
    float wy = __fadd_rn(sy, -(float)y0i);

    float tx = __fdiv_rn((float)ox, 223.0f);
    float sx = __fadd_rn((float)X0, __fmul_rn(tx, (float)(X1 - 1 - X0)));
    int x0i = (int)floorf(sx);
    int x1i = min(x0i + 1, X1 - 1);
    float wx = __fadd_rn(sx, -(float)x0i);

    const float* img = xin + ((size_t)b * 3 + c) * 448 * 448;
    auto fetch = [&](int y, int x) -> float {
        y -= 224; x -= 224;
        if ((unsigned)y < 448u && (unsigned)x < 448u) return img[y * 448 + x];
        return 0.f;
    };
    float f00 = fetch(y0i, x0i), f01 = fetch(y0i, x1i);
    float f10 = fetch(y1i, x0i), f11 = fetch(y1i, x1i);

    float top = (1.f - wx) * f00 + wx * f01;
    float bot = (1.f - wx) * f10 + wx * f11;
    float v = (1.f - wy) * top + wy * bot;

    out[(((size_t)bs * 3 + c) * OUTP + oy) * OUTP + ox] = v;
}

// ---------------- launch ----------------
extern "C" void kernel_launch(void* const* d_in, const int* in_sizes, int n_in,
                              void* d_out, int out_size) {
    const float* x       = (const float*)d_in[0];
    const float* rpn     = (const float*)d_in[1];
    const float* anchors = (const float*)d_in[2];
    const float* wd1 = (const float*)d_in[3];
    const float* bd1 = (const float*)d_in[4];
    const float* wd2 = (const float*)d_in[5];
    const float* bd2 = (const float*)d_in[6];
    const float* wd3 = (const float*)d_in[7];
    const float* bd3 = (const float*)d_in[8];
    const float* wt1 = (const float*)d_in[9];
    const float* bt1 = (const float*)d_in[10];
    const float* wt2 = (const float*)d_in[11];
    const float* bt2 = (const float*)d_in[12];
    const float* wt3 = (const float*)d_in[13];
    const float* bt3 = (const float*)d_in[14];
    float* out = (float*)d_out;

    prep_w<<<dim3(128, 8), 256>>>(wd1);
    prep_rpn<<<dim3(BATCH, 64), 256>>>(rpn);
    conv1_wmma<<<dim3(13, KS1), 256, DYNSMEM>>>();
    reduce_relu_kernel<<<(128 * GN + 255) / 256, 256>>>(bd1);
    conv2_part<<<dim3(BATCH, C2S), 392>>>(wd2);
    conv2_reduce<<<(BATCH * 128 * 49 + 255) / 256, 256>>>(bd2);
    conv3_part<<<dim3(BATCH, C3S), 128>>>(wd3);
    conv3_reduce<<<(BATCH * 128 * 16 + 255) / 256, 256>>>(bd3);
    heads_kernel<<<dim3(BATCH, 7), 256>>>(wt1, bt1, wt2, bt2, wt3, bt3);
    nms_topk_kernel<<<BATCH, 1024>>>(anchors, out);
    crop_kernel<<<dim3(OUTP, 3, BATCH * TOPN), OUTP>>>(x, out);
}